// round 5
// baseline (speedup 1.0000x reference)
#include <cuda_runtime.h>

// heightfield: [16,1,512,512] f32 -> same shape.
// out[w] = 1 - clip( max_{r=1..16}( pad(row)[w+r] - r/10 ) - row[w], 0, 1 )
// g(x) = s[x] - 0.1*col(x). Each thread: one output quad, five overlapped
// aligned float4 loads covering its 20-input footprint. No shuffles/smem.

#define IM 512
#define NEG (-1e30f)
#define THREADS 256

__global__ __launch_bounds__(THREADS) void shadow_ov(const float* __restrict__ in,
                                                     float* __restrict__ out) {
    const int gtid = blockIdx.x * blockDim.x + threadIdx.x;
    const int c0 = gtid << 2;              // global element index (row-major)
    const int col = c0 & (IM - 1);         // column within row

    const float* p = in + c0;

    float g[20];
    #pragma unroll
    for (int i = 0; i < 5; ++i) {
        if (col + 4 * i <= IM - 4) {       // quad fully inside this row
            float4 v = *reinterpret_cast<const float4*>(p + 4 * i);
            g[4*i+0] = fmaf((float)(col + 4*i + 0), -0.1f, v.x);
            g[4*i+1] = fmaf((float)(col + 4*i + 1), -0.1f, v.y);
            g[4*i+2] = fmaf((float)(col + 4*i + 2), -0.1f, v.z);
            g[4*i+3] = fmaf((float)(col + 4*i + 3), -0.1f, v.w);
        } else {                           // beyond row end: pad (never wins)
            g[4*i+0] = NEG; g[4*i+1] = NEG; g[4*i+2] = NEG; g[4*i+3] = NEG;
        }
    }

    // common max over k = 4..16 (shared by all four windows)
    float cm = g[4];
    #pragma unroll
    for (int k = 5; k <= 16; ++k) cm = fmaxf(cm, g[k]);

    // window j: k in [j+1, j+16]
    const float a = fmaxf(g[2], g[3]);
    const float b = fmaxf(g[17], g[18]);
    const float m0 = fmaxf(cm, fmaxf(g[1], a));
    const float m1 = fmaxf(cm, fmaxf(a, g[17]));
    const float m2 = fmaxf(cm, fmaxf(g[3], b));
    const float m3 = fmaxf(cm, fmaxf(b, g[19]));

    float4 o;
    o.x = 1.0f - fminf(fmaxf(m0 - g[0], 0.0f), 1.0f);
    o.y = 1.0f - fminf(fmaxf(m1 - g[1], 0.0f), 1.0f);
    o.z = 1.0f - fminf(fmaxf(m2 - g[2], 0.0f), 1.0f);
    o.w = 1.0f - fminf(fmaxf(m3 - g[3], 0.0f), 1.0f);

    *reinterpret_cast<float4*>(out + c0) = o;
}

extern "C" void kernel_launch(void* const* d_in, const int* in_sizes, int n_in,
                              void* d_out, int out_size) {
    const float* in = (const float*)d_in[0];
    float* out = (float*)d_out;
    const int n = in_sizes[0];                 // 4,194,304
    const int threads_total = n / 4;           // 1,048,576
    shadow_ov<<<threads_total / THREADS, THREADS>>>(in, out);
}

// round 6
// speedup vs baseline: 1.0557x; 1.0557x over previous
#include <cuda_runtime.h>

// heightfield: [16,1,512,512] f32 -> same shape.
// out[w] = 1 - clip( max_{r=1..16}( pad(row)[w+r] - r/10 ) - row[w], 0, 1 )
// Thread-local bias: g[k] = v[k] - 0.1*k (k = 0..19 compile-time constants;
// valid because all comparisons stay inside one thread's footprint).
// out = saturate(1 + g[j] - m_j). Five overlapped aligned float4 loads, MLP=5.

#define IM 512
#define NEG (-1e30f)
#define THREADS 256

__global__ __launch_bounds__(THREADS) void shadow_ov2(const float* __restrict__ in,
                                                      float* __restrict__ out) {
    const int gtid = blockIdx.x * blockDim.x + threadIdx.x;
    const int c0 = gtid << 2;              // element index (row-major)
    const int col = c0 & (IM - 1);         // column within row

    const float* p = in + c0;

    float g[20];
    // quad 0 always fully in-row (c0 <= 508)
    {
        float4 v = *reinterpret_cast<const float4*>(p);
        g[0] = v.x;                         // bias 0.0
        g[1] = v.y - 0.1f;
        g[2] = v.z - 0.2f;
        g[3] = v.w - 0.3f;
    }
    #pragma unroll
    for (int i = 1; i < 5; ++i) {
        if (col <= IM - 4 - 4 * i) {        // quad fully inside this row
            float4 v = *reinterpret_cast<const float4*>(p + 4 * i);
            g[4*i+0] = v.x - 0.1f * (4*i+0);
            g[4*i+1] = v.y - 0.1f * (4*i+1);
            g[4*i+2] = v.z - 0.1f * (4*i+2);
            g[4*i+3] = v.w - 0.1f * (4*i+3);
        } else {                            // beyond row end: never wins
            g[4*i+0] = NEG; g[4*i+1] = NEG; g[4*i+2] = NEG; g[4*i+3] = NEG;
        }
    }

    // common max over k = 4..16 (shared by all four windows)
    float cm = g[4];
    #pragma unroll
    for (int k = 5; k <= 16; ++k) cm = fmaxf(cm, g[k]);

    // window j: k in [j+1, j+16]
    const float a = fmaxf(g[2], g[3]);
    const float b = fmaxf(g[17], g[18]);
    const float m0 = fmaxf(cm, fmaxf(g[1], a));
    const float m1 = fmaxf(cm, fmaxf(a, g[17]));
    const float m2 = fmaxf(cm, fmaxf(g[3], b));
    const float m3 = fmaxf(cm, fmaxf(b, g[19]));

    float4 o;
    o.x = __saturatef(1.0f + (g[0] - m0));
    o.y = __saturatef(1.0f + (g[1] - m1));
    o.z = __saturatef(1.0f + (g[2] - m2));
    o.w = __saturatef(1.0f + (g[3] - m3));

    *reinterpret_cast<float4*>(out + c0) = o;
}

extern "C" void kernel_launch(void* const* d_in, const int* in_sizes, int n_in,
                              void* d_out, int out_size) {
    const float* in = (const float*)d_in[0];
    float* out = (float*)d_out;
    const int n = in_sizes[0];                 // 4,194,304
    const int threads_total = n / 4;           // 1,048,576
    shadow_ov2<<<threads_total / THREADS, THREADS>>>(in, out);
}